// round 4
// baseline (speedup 1.0000x reference)
#include <cuda_runtime.h>
#include <cstdint>

#define B_SZ 2048
#define T_SZ 256
#define IN_SZ 65
#define H_SZ 64
#define G_SZ 256           // 4*H
#define BR 16              // batch rows per block
#define NP 8               // row pairs per block
#define PST 10             // ull stride per k-row (80B, keeps 16B alignment)
#define NTH 512

typedef unsigned long long ull;

__device__ __forceinline__ ull ffma2(ull a, ull b, ull c) {
    ull d;
    asm("fma.rn.f32x2 %0, %1, %2, %3;" : "=l"(d) : "l"(a), "l"(b), "l"(c));
    return d;
}
__device__ __forceinline__ ull fadd2(ull a, ull b) {
    ull d;
    asm("add.rn.f32x2 %0, %1, %2;" : "=l"(d) : "l"(a), "l"(b));
    return d;
}
__device__ __forceinline__ ull fdup(float v) {
    ull d;
    asm("mov.b64 %0, {%1, %1};" : "=l"(d) : "f"(v));
    return d;
}
__device__ __forceinline__ ull fpack(float lo, float hi) {
    ull d;
    asm("mov.b64 %0, {%1, %2};" : "=l"(d) : "f"(lo), "f"(hi));
    return d;
}
__device__ __forceinline__ void funpack(ull v, float& lo, float& hi) {
    asm("mov.b64 {%0, %1}, %2;" : "=f"(lo), "=f"(hi) : "l"(v));
}
__device__ __forceinline__ float ex2f(float x) {
    float y; asm("ex2.approx.f32 %0, %1;" : "=f"(y) : "f"(x)); return y;
}
__device__ __forceinline__ float rcpf(float x) {
    float y; asm("rcp.approx.f32 %0, %1;" : "=f"(y) : "f"(x)); return y;
}
__device__ __forceinline__ float sigf(float x) {
    return rcpf(1.0f + ex2f(-1.4426950408889634f * x));
}
__device__ __forceinline__ float tanhf_(float x) {
    return fmaf(2.0f, rcpf(1.0f + ex2f(-2.8853900817779268f * x)), -1.0f);
}

__global__ __launch_bounds__(NTH, 1)
void lstm_fused_kernel(const float* __restrict__ x,
                       const float* __restrict__ Wih,
                       const float* __restrict__ Whh,
                       const float* __restrict__ bih,
                       const float* __restrict__ bhh,
                       const float* __restrict__ fcW,
                       const float* __restrict__ fcb,
                       float* __restrict__ out) {
    // small static smem: all hot loads are warp-uniform broadcasts
    __shared__ ull xbuf2[IN_SZ * PST];   // x row-pairs,   [k][p]
    __shared__ ull h2buf[IN_SZ * PST];   // h row-pairs,   [k][p]  (row 64 = zero pad)
    __shared__ ull gA[NP * G_SZ];        // x-part partial gates [p][gate]
    __shared__ ull gB[NP * G_SZ];        // h-part partial gates [p][gate]

    const int tid = threadIdx.x;
    const int b0  = blockIdx.x * BR;
    const bool isA = tid < 256;
    const int j = isA ? tid : tid - 256;       // owned gate column 0..255

    // ---- weights -> registers (one-time) ----
    float w_[IN_SZ];
    if (isA) {
#pragma unroll
        for (int k = 0; k < IN_SZ; ++k) w_[k] = Wih[j * IN_SZ + k];
    } else {
#pragma unroll
        for (int k = 0; k < H_SZ; ++k) w_[k] = Whh[j * H_SZ + k];
        w_[H_SZ] = 0.0f;                       // pads the unified 65-k loop
    }

    // ---- zero h2buf (incl. pad row), fill xbuf2 for t=0 ----
    for (int i = tid; i < IN_SZ * PST; i += NTH) h2buf[i] = 0ULL;
    {
        const int p = tid >> 6, k = tid & 63;
        const float* xp = x + (size_t)(b0 + 2 * p) * T_SZ * IN_SZ;
        xbuf2[k * PST + p] = fpack(xp[k], xp[(size_t)T_SZ * IN_SZ + k]);
        if (tid < NP) {
            const float* xq = x + (size_t)(b0 + 2 * tid) * T_SZ * IN_SZ;
            xbuf2[64 * PST + tid] = fpack(xq[64], xq[(size_t)T_SZ * IN_SZ + 64]);
        }
    }

    // ---- update-phase mapping: pair up, unit uu ----
    const int up = tid >> 6;           // 0..7
    const int uu = tid & 63;           // 0..63
    const float bI = bih[uu]       + bhh[uu];
    const float bF = bih[64 + uu]  + bhh[64 + uu];
    const float bG = bih[128 + uu] + bhh[128 + uu];
    const float bO = bih[192 + uu] + bhh[192 + uu];
    float cLo = 0.0f, cHi = 0.0f;

    const ull* src = isA ? xbuf2 : h2buf;
    ull* gb = isA ? gA : gB;

    __syncthreads();

    for (int t = 0; t < T_SZ; ++t) {
        // ---- prefetch x[t+1] (latency covered by MAC phase) ----
        float xa = 0.f, xb = 0.f, xc = 0.f, xd = 0.f;
        const bool hasNext = (t + 1 < T_SZ);
        const int pp = tid >> 6, kk = tid & 63;
        if (hasNext) {
            const float* xp = x + ((size_t)(b0 + 2 * pp) * T_SZ + (t + 1)) * IN_SZ;
            xa = xp[kk];
            xb = xp[(size_t)T_SZ * IN_SZ + kk];
            if (tid < NP) {
                const float* xq = x + ((size_t)(b0 + 2 * tid) * T_SZ + (t + 1)) * IN_SZ;
                xc = xq[64];
                xd = xq[(size_t)T_SZ * IN_SZ + 64];
            }
        }

        // ---- MAC phase: gate j for 8 row-pairs; w in regs, h/x broadcast ----
        ull a0 = 0, a1 = 0, a2 = 0, a3 = 0, a4 = 0, a5 = 0, a6 = 0, a7 = 0;
#pragma unroll
        for (int k = 0; k < IN_SZ; ++k) {
            const ull wd = fdup(w_[k]);
            const ull* s = src + k * PST;
            ulonglong2 p01 = *(const ulonglong2*)(s);
            ulonglong2 p23 = *(const ulonglong2*)(s + 2);
            ulonglong2 p45 = *(const ulonglong2*)(s + 4);
            ulonglong2 p67 = *(const ulonglong2*)(s + 6);
            a0 = ffma2(wd, p01.x, a0); a1 = ffma2(wd, p01.y, a1);
            a2 = ffma2(wd, p23.x, a2); a3 = ffma2(wd, p23.y, a3);
            a4 = ffma2(wd, p45.x, a4); a5 = ffma2(wd, p45.y, a5);
            a6 = ffma2(wd, p67.x, a6); a7 = ffma2(wd, p67.y, a7);
        }
        gb[0 * G_SZ + j] = a0; gb[1 * G_SZ + j] = a1;
        gb[2 * G_SZ + j] = a2; gb[3 * G_SZ + j] = a3;
        gb[4 * G_SZ + j] = a4; gb[5 * G_SZ + j] = a5;
        gb[6 * G_SZ + j] = a6; gb[7 * G_SZ + j] = a7;
        __syncthreads();

        // ---- update phase: unit uu, rows (2*up, 2*up+1) ----
        {
            ull sI = fadd2(gA[up * G_SZ + uu],       gB[up * G_SZ + uu]);
            ull sF = fadd2(gA[up * G_SZ + 64 + uu],  gB[up * G_SZ + 64 + uu]);
            ull sG = fadd2(gA[up * G_SZ + 128 + uu], gB[up * G_SZ + 128 + uu]);
            ull sO = fadd2(gA[up * G_SZ + 192 + uu], gB[up * G_SZ + 192 + uu]);
            float iL, iH, fL, fH, gL, gH, oL, oH;
            funpack(sI, iL, iH); funpack(sF, fL, fH);
            funpack(sG, gL, gH); funpack(sO, oL, oH);

            float iv = sigf(iL + bI);
            float fv = sigf(fL + bF);
            float gv = tanhf_(gL + bG);
            float ov = sigf(oL + bO);
            cLo = fv * cLo + iv * gv;
            float hLo = ov * tanhf_(cLo);

            iv = sigf(iH + bI);
            fv = sigf(fH + bF);
            gv = tanhf_(gH + bG);
            ov = sigf(oH + bO);
            cHi = fv * cHi + iv * gv;
            float hHi = ov * tanhf_(cHi);

            h2buf[uu * PST + up] = fpack(hLo, hHi);
        }

        // ---- commit prefetched x[t+1] ----
        if (hasNext) {
            xbuf2[kk * PST + pp] = fpack(xa, xb);
            if (tid < NP) xbuf2[64 * PST + tid] = fpack(xc, xd);
        }
        __syncthreads();
    }

    // ---- final FC head: out[b][o] = sigmoid(h . fcW[o] + fcb[o]) ----
    if (tid < BR * 7) {
        int r = tid / 7;
        int o = tid - r * 7;
        float s = fcb[o];
        const float* wrow = fcW + o * H_SZ;
#pragma unroll 8
        for (int u = 0; u < H_SZ; ++u) {
            float lo, hi;
            funpack(h2buf[u * PST + (r >> 1)], lo, hi);
            s += wrow[u] * ((r & 1) ? hi : lo);
        }
        out[(size_t)(b0 + r) * 7 + o] = sigf(s);
    }
}

extern "C" void kernel_launch(void* const* d_in, const int* in_sizes, int n_in,
                              void* d_out, int out_size) {
    const float* x    = (const float*)d_in[0];
    const float* Wih  = (const float*)d_in[1];
    const float* Whh  = (const float*)d_in[2];
    const float* bih  = (const float*)d_in[3];
    const float* bhh  = (const float*)d_in[4];
    const float* fcW  = (const float*)d_in[5];
    const float* fcb  = (const float*)d_in[6];
    float* out = (float*)d_out;

    lstm_fused_kernel<<<B_SZ / BR, NTH>>>(x, Wih, Whh, bih, bhh, fcW, fcb, out);
}

// round 5
// speedup vs baseline: 1.3935x; 1.3935x over previous
#include <cuda_runtime.h>
#include <cstdint>

#define B_SZ 2048
#define T_SZ 256
#define IN_SZ 65
#define H_SZ 64
#define G_SZ 256           // 4*H
#define KK 129             // IN_SZ + H_SZ
#define BR 16              // batch rows per block
#define NP 8               // row pairs per block
#define PST 10             // ull stride per k-row (80B, keeps 16B alignment)
#define KSPL 43            // k per part (3 * 43 = 129)
#define NTH 768

typedef unsigned long long ull;

__device__ __forceinline__ ull ffma2(ull a, ull b, ull c) {
    ull d;
    asm("fma.rn.f32x2 %0, %1, %2, %3;" : "=l"(d) : "l"(a), "l"(b), "l"(c));
    return d;
}
__device__ __forceinline__ ull fadd2(ull a, ull b) {
    ull d;
    asm("add.rn.f32x2 %0, %1, %2;" : "=l"(d) : "l"(a), "l"(b));
    return d;
}
__device__ __forceinline__ ull fdup(float v) {
    ull d;
    asm("mov.b64 %0, {%1, %1};" : "=l"(d) : "f"(v));
    return d;
}
__device__ __forceinline__ ull fpack(float lo, float hi) {
    ull d;
    asm("mov.b64 %0, {%1, %2};" : "=l"(d) : "f"(lo), "f"(hi));
    return d;
}
__device__ __forceinline__ void funpack(ull v, float& lo, float& hi) {
    asm("mov.b64 {%0, %1}, %2;" : "=f"(lo), "=f"(hi) : "l"(v));
}
__device__ __forceinline__ float ex2f(float x) {
    float y; asm("ex2.approx.f32 %0, %1;" : "=f"(y) : "f"(x)); return y;
}
__device__ __forceinline__ float rcpf(float x) {
    float y; asm("rcp.approx.f32 %0, %1;" : "=f"(y) : "f"(x)); return y;
}
__device__ __forceinline__ float sigf(float x) {
    return rcpf(1.0f + ex2f(-1.4426950408889634f * x));
}
__device__ __forceinline__ float tanhf_(float x) {
    return fmaf(2.0f, rcpf(1.0f + ex2f(-2.8853900817779268f * x)), -1.0f);
}

// dynamic smem layout (bytes)
#define SB_BYTES   (KK * PST * 8)              // 10320  sbuf row-pairs [129][PST] (x: k<65, h: k>=65)
#define GB_BYTES   (3 * NP * G_SZ * 8)         // 49152  partial gates [part][p][gate]
#define BIAS_BYTES (G_SZ * 4)                  // 1024
#define SMEM_TOTAL (SB_BYTES + GB_BYTES + BIAS_BYTES)   // 60496

__global__ __launch_bounds__(NTH, 1)
void lstm_fused_kernel(const float* __restrict__ x,
                       const float* __restrict__ Wih,
                       const float* __restrict__ Whh,
                       const float* __restrict__ bih,
                       const float* __restrict__ bhh,
                       const float* __restrict__ fcW,
                       const float* __restrict__ fcb,
                       float* __restrict__ out) {
    extern __shared__ char sm_raw[];
    ull*   sbuf = (ull*)sm_raw;                          // [129][PST]
    ull*   gbuf = (ull*)(sm_raw + SB_BYTES);             // [3][8][256]
    float* bias = (float*)(sm_raw + SB_BYTES + GB_BYTES); // [256]

    const int tid  = threadIdx.x;
    const int b0   = blockIdx.x * BR;
    const int j    = tid & 255;         // owned gate column
    const int part = tid >> 8;          // k-part 0..2
    const int k0   = part * KSPL;

    // ---- weights -> registers (one-time): w_[i] = W[j][k0+i] ----
    float w_[KSPL];
#pragma unroll
    for (int i = 0; i < KSPL; ++i) {
        int gk = k0 + i;
        w_[i] = (gk < IN_SZ) ? Wih[j * IN_SZ + gk]
                             : Whh[j * H_SZ + (gk - IN_SZ)];
    }

    // ---- init: zero h region, fill x row-pairs for t=0, combined bias ----
    for (int i = tid; i < H_SZ * PST; i += NTH) sbuf[IN_SZ * PST + i] = 0ULL;
    const int pp = tid & 7;             // row pair 0..7 (prefetch role, tid<520)
    const int kk = tid >> 3;            // k 0..64
    if (tid < 520) {
        const float* xp = x + (size_t)(b0 + 2 * pp) * T_SZ * IN_SZ + kk;
        sbuf[kk * PST + pp] = fpack(xp[0], xp[(size_t)T_SZ * IN_SZ]);
    }
    if (tid < G_SZ) bias[tid] = bih[tid] + bhh[tid];

    // ---- update-phase mapping (tid < 512): pair up, unit uu ----
    const int up = tid >> 6;            // 0..7 (mod 8 for tid<512)
    const int uu = tid & 63;            // 0..63
    float cLo = 0.0f, cHi = 0.0f;

    __syncthreads();

    for (int t = 0; t < T_SZ; ++t) {
        // ---- prefetch x[t+1] (latency covered by MAC phase) ----
        float xa = 0.f, xb = 0.f;
        const bool hasNext = (t + 1 < T_SZ);
        if (tid < 520 && hasNext) {
            const float* xp = x + ((size_t)(b0 + 2 * pp) * T_SZ + (t + 1)) * IN_SZ + kk;
            xa = xp[0];
            xb = xp[(size_t)T_SZ * IN_SZ];
        }

        // ---- MAC phase: gate j, 8 row-pairs, k-part [k0, k0+43) ----
        ull a0 = 0, a1 = 0, a2 = 0, a3 = 0, a4 = 0, a5 = 0, a6 = 0, a7 = 0;
        const ull* sp = sbuf + k0 * PST;
#pragma unroll
        for (int k = 0; k < KSPL; ++k) {
            const ull wd = fdup(w_[k]);
            ulonglong2 p01 = *(const ulonglong2*)(sp);
            ulonglong2 p23 = *(const ulonglong2*)(sp + 2);
            ulonglong2 p45 = *(const ulonglong2*)(sp + 4);
            ulonglong2 p67 = *(const ulonglong2*)(sp + 6);
            sp += PST;
            a0 = ffma2(wd, p01.x, a0); a1 = ffma2(wd, p01.y, a1);
            a2 = ffma2(wd, p23.x, a2); a3 = ffma2(wd, p23.y, a3);
            a4 = ffma2(wd, p45.x, a4); a5 = ffma2(wd, p45.y, a5);
            a6 = ffma2(wd, p67.x, a6); a7 = ffma2(wd, p67.y, a7);
        }
        {
            ull* g = gbuf + part * (NP * G_SZ) + j;
            g[0 * G_SZ] = a0; g[1 * G_SZ] = a1;
            g[2 * G_SZ] = a2; g[3 * G_SZ] = a3;
            g[4 * G_SZ] = a4; g[5 * G_SZ] = a5;
            g[6 * G_SZ] = a6; g[7 * G_SZ] = a7;
        }
        __syncthreads();

        // ---- update phase (tid < 512): unit uu, rows (2*up, 2*up+1) ----
        if (tid < 512) {
            const ull* g0 = gbuf + up * G_SZ;
            ull sI = fadd2(fadd2(g0[uu],       g0[NP * G_SZ + uu]),       g0[2 * NP * G_SZ + uu]);
            ull sF = fadd2(fadd2(g0[64 + uu],  g0[NP * G_SZ + 64 + uu]),  g0[2 * NP * G_SZ + 64 + uu]);
            ull sG = fadd2(fadd2(g0[128 + uu], g0[NP * G_SZ + 128 + uu]), g0[2 * NP * G_SZ + 128 + uu]);
            ull sO = fadd2(fadd2(g0[192 + uu], g0[NP * G_SZ + 192 + uu]), g0[2 * NP * G_SZ + 192 + uu]);
            float iL, iH, fL, fH, gL, gH, oL, oH;
            funpack(sI, iL, iH); funpack(sF, fL, fH);
            funpack(sG, gL, gH); funpack(sO, oL, oH);
            const float bI = bias[uu];
            const float bF = bias[64 + uu];
            const float bG = bias[128 + uu];
            const float bO = bias[192 + uu];

            float iv = sigf(iL + bI);
            float fv = sigf(fL + bF);
            float gv = tanhf_(gL + bG);
            float ov = sigf(oL + bO);
            cLo = fv * cLo + iv * gv;
            float hLo = ov * tanhf_(cLo);

            iv = sigf(iH + bI);
            fv = sigf(fH + bF);
            gv = tanhf_(gH + bG);
            ov = sigf(oH + bO);
            cHi = fv * cHi + iv * gv;
            float hHi = ov * tanhf_(cHi);

            sbuf[(IN_SZ + uu) * PST + up] = fpack(hLo, hHi);
        }

        // ---- commit prefetched x[t+1] ----
        if (tid < 520 && hasNext) {
            sbuf[kk * PST + pp] = fpack(xa, xb);
        }
        __syncthreads();
    }

    // ---- final FC head: out[b][o] = sigmoid(h . fcW[o] + fcb[o]) ----
    if (tid < BR * 7) {
        int r = tid / 7;
        int o = tid - r * 7;
        float s = fcb[o];
        const float* wrow = fcW + o * H_SZ;
#pragma unroll 8
        for (int u = 0; u < H_SZ; ++u) {
            float lo, hi;
            funpack(sbuf[(IN_SZ + u) * PST + (r >> 1)], lo, hi);
            s += wrow[u] * ((r & 1) ? hi : lo);
        }
        out[(size_t)(b0 + r) * 7 + o] = sigf(s);
    }
}

extern "C" void kernel_launch(void* const* d_in, const int* in_sizes, int n_in,
                              void* d_out, int out_size) {
    const float* x    = (const float*)d_in[0];
    const float* Wih  = (const float*)d_in[1];
    const float* Whh  = (const float*)d_in[2];
    const float* bih  = (const float*)d_in[3];
    const float* bhh  = (const float*)d_in[4];
    const float* fcW  = (const float*)d_in[5];
    const float* fcb  = (const float*)d_in[6];
    float* out = (float*)d_out;

    cudaFuncSetAttribute(lstm_fused_kernel,
                         cudaFuncAttributeMaxDynamicSharedMemorySize, SMEM_TOTAL);
    lstm_fused_kernel<<<B_SZ / BR, NTH, SMEM_TOTAL>>>(x, Wih, Whh, bih, bhh, fcW, fcb, out);
}

// round 6
// speedup vs baseline: 1.8646x; 1.3381x over previous
#include <cuda_runtime.h>
#include <cstdint>

#define B_SZ 2048
#define T_SZ 256
#define IN_SZ 65
#define H_SZ 64
#define G_SZ 256           // 4*H
#define KK 129             // IN_SZ + H_SZ
#define BR 16              // batch rows per block
#define NP 8               // row pairs per block
#define PST 10             // ull stride per k-row (80B, keeps 16B alignment)
#define KSPL 43            // k per part (3 * 43 = 129)
#define NTH 384

typedef unsigned long long ull;

__device__ __forceinline__ ull ffma2(ull a, ull b, ull c) {
    ull d;
    asm("fma.rn.f32x2 %0, %1, %2, %3;" : "=l"(d) : "l"(a), "l"(b), "l"(c));
    return d;
}
__device__ __forceinline__ ull fadd2(ull a, ull b) {
    ull d;
    asm("add.rn.f32x2 %0, %1, %2;" : "=l"(d) : "l"(a), "l"(b));
    return d;
}
__device__ __forceinline__ ull fdup(float v) {
    ull d;
    asm("mov.b64 %0, {%1, %1};" : "=l"(d) : "f"(v));
    return d;
}
__device__ __forceinline__ ull fpack(float lo, float hi) {
    ull d;
    asm("mov.b64 %0, {%1, %2};" : "=l"(d) : "f"(lo), "f"(hi));
    return d;
}
__device__ __forceinline__ void funpack(ull v, float& lo, float& hi) {
    asm("mov.b64 {%0, %1}, %2;" : "=f"(lo), "=f"(hi) : "l"(v));
}
__device__ __forceinline__ float ex2f(float x) {
    float y; asm("ex2.approx.f32 %0, %1;" : "=f"(y) : "f"(x)); return y;
}
__device__ __forceinline__ float rcpf(float x) {
    float y; asm("rcp.approx.f32 %0, %1;" : "=f"(y) : "f"(x)); return y;
}
__device__ __forceinline__ float sigf(float x) {
    return rcpf(1.0f + ex2f(-1.4426950408889634f * x));
}
__device__ __forceinline__ float tanhf_(float x) {
    return fmaf(2.0f, rcpf(1.0f + ex2f(-2.8853900817779268f * x)), -1.0f);
}

// dynamic smem layout (bytes)
#define SB_BYTES   (KK * PST * 8)              // 10320  sbuf row-pairs [129][PST] (x: k<65, h: k>=65)
#define GB_BYTES   (3 * NP * G_SZ * 8)         // 49152  partial gates [part][p][gate]
#define BIAS_BYTES (G_SZ * 4)                  // 1024
#define SMEM_TOTAL (SB_BYTES + GB_BYTES + BIAS_BYTES)   // 60496

__global__ __launch_bounds__(NTH, 1)
void lstm_fused_kernel(const float* __restrict__ x,
                       const float* __restrict__ Wih,
                       const float* __restrict__ Whh,
                       const float* __restrict__ bih,
                       const float* __restrict__ bhh,
                       const float* __restrict__ fcW,
                       const float* __restrict__ fcb,
                       float* __restrict__ out) {
    extern __shared__ char sm_raw[];
    ull*   sbuf = (ull*)sm_raw;                           // [129][PST]
    ull*   gbuf = (ull*)(sm_raw + SB_BYTES);              // [3][8][256]
    float* bias = (float*)(sm_raw + SB_BYTES + GB_BYTES); // [256]

    const int tid  = threadIdx.x;
    const int b0   = blockIdx.x * BR;
    const int part = tid >> 7;          // 0..2
    const int jh   = tid & 127;
    const int j0   = jh;                // owned gate columns j0 and j0+128
    const int k0   = part * KSPL;

    // ---- weights -> registers (one-time) ----
    float w0_[KSPL], w1_[KSPL];
#pragma unroll
    for (int i = 0; i < KSPL; ++i) {
        int gk = k0 + i;
        if (gk < IN_SZ) {
            w0_[i] = Wih[j0 * IN_SZ + gk];
            w1_[i] = Wih[(j0 + 128) * IN_SZ + gk];
        } else {
            w0_[i] = Whh[j0 * H_SZ + (gk - IN_SZ)];
            w1_[i] = Whh[(j0 + 128) * H_SZ + (gk - IN_SZ)];
        }
    }

    // ---- init: zero h region, fill x row-pairs for t=0, combined bias ----
    for (int i = tid; i < H_SZ * PST; i += NTH) sbuf[IN_SZ * PST + i] = 0ULL;
    for (int idx = tid; idx < 520; idx += NTH) {
        const int p = idx & 7, k = idx >> 3;
        const float* xp = x + (size_t)(b0 + 2 * p) * T_SZ * IN_SZ + k;
        sbuf[k * PST + p] = fpack(xp[0], xp[(size_t)T_SZ * IN_SZ]);
    }
    if (tid < G_SZ) bias[tid] = bih[tid] + bhh[tid];

    // ---- update-phase mapping (tid < 256): unit uu, pairs up0 and up0+4 ----
    const int up0 = tid >> 6;           // 0..3 for tid<256
    const int uu  = tid & 63;           // 0..63
    float c0L = 0.0f, c0H = 0.0f, c1L = 0.0f, c1H = 0.0f;

    __syncthreads();

    for (int t = 0; t < T_SZ; ++t) {
        // ---- prefetch x[t+1] (latency covered by MAC phase) ----
        float xa0 = 0.f, xb0 = 0.f, xa1 = 0.f, xb1 = 0.f;
        const bool hasNext = (t + 1 < T_SZ);
        if (hasNext) {
            {
                const int p = tid & 7, k = tid >> 3;
                const float* xp = x + ((size_t)(b0 + 2 * p) * T_SZ + (t + 1)) * IN_SZ + k;
                xa0 = xp[0];
                xb0 = xp[(size_t)T_SZ * IN_SZ];
            }
            if (tid < 136) {
                const int idx = tid + NTH;
                const int p = idx & 7, k = idx >> 3;
                const float* xp = x + ((size_t)(b0 + 2 * p) * T_SZ + (t + 1)) * IN_SZ + k;
                xa1 = xp[0];
                xb1 = xp[(size_t)T_SZ * IN_SZ];
            }
        }

        // ---- MAC phase: gates j0 & j0+128, 8 row-pairs, k-part [k0, k0+43) ----
        ull a0 = 0, a1 = 0, a2 = 0, a3 = 0, a4 = 0, a5 = 0, a6 = 0, a7 = 0;
        ull b0r = 0, b1r = 0, b2r = 0, b3r = 0, b4r = 0, b5r = 0, b6r = 0, b7r = 0;
        const ull* sp = sbuf + k0 * PST;
#pragma unroll
        for (int k = 0; k < KSPL; ++k) {
            const ull wd0 = fdup(w0_[k]);
            const ull wd1 = fdup(w1_[k]);
            ulonglong2 p01 = *(const ulonglong2*)(sp);
            ulonglong2 p23 = *(const ulonglong2*)(sp + 2);
            ulonglong2 p45 = *(const ulonglong2*)(sp + 4);
            ulonglong2 p67 = *(const ulonglong2*)(sp + 6);
            sp += PST;
            a0  = ffma2(wd0, p01.x, a0);  a1  = ffma2(wd0, p01.y, a1);
            a2  = ffma2(wd0, p23.x, a2);  a3  = ffma2(wd0, p23.y, a3);
            a4  = ffma2(wd0, p45.x, a4);  a5  = ffma2(wd0, p45.y, a5);
            a6  = ffma2(wd0, p67.x, a6);  a7  = ffma2(wd0, p67.y, a7);
            b0r = ffma2(wd1, p01.x, b0r); b1r = ffma2(wd1, p01.y, b1r);
            b2r = ffma2(wd1, p23.x, b2r); b3r = ffma2(wd1, p23.y, b3r);
            b4r = ffma2(wd1, p45.x, b4r); b5r = ffma2(wd1, p45.y, b5r);
            b6r = ffma2(wd1, p67.x, b6r); b7r = ffma2(wd1, p67.y, b7r);
        }
        {
            ull* g = gbuf + part * (NP * G_SZ) + j0;
            g[0 * G_SZ] = a0;  g[1 * G_SZ] = a1;
            g[2 * G_SZ] = a2;  g[3 * G_SZ] = a3;
            g[4 * G_SZ] = a4;  g[5 * G_SZ] = a5;
            g[6 * G_SZ] = a6;  g[7 * G_SZ] = a7;
            ull* g2 = g + 128;
            g2[0 * G_SZ] = b0r; g2[1 * G_SZ] = b1r;
            g2[2 * G_SZ] = b2r; g2[3 * G_SZ] = b3r;
            g2[4 * G_SZ] = b4r; g2[5 * G_SZ] = b5r;
            g2[6 * G_SZ] = b6r; g2[7 * G_SZ] = b7r;
        }
        __syncthreads();

        // ---- update phase (tid < 256): unit uu, row-pairs up0 and up0+4 ----
        if (tid < 256) {
            const float bI = bias[uu];
            const float bF = bias[64 + uu];
            const float bG = bias[128 + uu];
            const float bO = bias[192 + uu];
#pragma unroll
            for (int half = 0; half < 2; ++half) {
                const int up = up0 + half * 4;
                float& cL = half ? c1L : c0L;
                float& cH = half ? c1H : c0H;
                const ull* g0 = gbuf + up * G_SZ;
                ull sI = fadd2(fadd2(g0[uu],       g0[NP * G_SZ + uu]),       g0[2 * NP * G_SZ + uu]);
                ull sF = fadd2(fadd2(g0[64 + uu],  g0[NP * G_SZ + 64 + uu]),  g0[2 * NP * G_SZ + 64 + uu]);
                ull sG = fadd2(fadd2(g0[128 + uu], g0[NP * G_SZ + 128 + uu]), g0[2 * NP * G_SZ + 128 + uu]);
                ull sO = fadd2(fadd2(g0[192 + uu], g0[NP * G_SZ + 192 + uu]), g0[2 * NP * G_SZ + 192 + uu]);
                float iL, iH, fL, fH, gL, gH, oL, oH;
                funpack(sI, iL, iH); funpack(sF, fL, fH);
                funpack(sG, gL, gH); funpack(sO, oL, oH);

                float iv = sigf(iL + bI);
                float fv = sigf(fL + bF);
                float gv = tanhf_(gL + bG);
                float ov = sigf(oL + bO);
                cL = fv * cL + iv * gv;
                float hLo = ov * tanhf_(cL);

                iv = sigf(iH + bI);
                fv = sigf(fH + bF);
                gv = tanhf_(gH + bG);
                ov = sigf(oH + bO);
                cH = fv * cH + iv * gv;
                float hHi = ov * tanhf_(cH);

                sbuf[(IN_SZ + uu) * PST + up] = fpack(hLo, hHi);
            }
        }

        // ---- commit prefetched x[t+1] ----
        if (hasNext) {
            {
                const int p = tid & 7, k = tid >> 3;
                sbuf[k * PST + p] = fpack(xa0, xb0);
            }
            if (tid < 136) {
                const int idx = tid + NTH;
                const int p = idx & 7, k = idx >> 3;
                sbuf[k * PST + p] = fpack(xa1, xb1);
            }
        }
        __syncthreads();
    }

    // ---- final FC head: out[b][o] = sigmoid(h . fcW[o] + fcb[o]) ----
    if (tid < BR * 7) {
        int r = tid / 7;
        int o = tid - r * 7;
        float s = fcb[o];
        const float* wrow = fcW + o * H_SZ;
#pragma unroll 8
        for (int u = 0; u < H_SZ; ++u) {
            float lo, hi;
            funpack(sbuf[(IN_SZ + u) * PST + (r >> 1)], lo, hi);
            s += wrow[u] * ((r & 1) ? hi : lo);
        }
        out[(size_t)(b0 + r) * 7 + o] = sigf(s);
    }
}

extern "C" void kernel_launch(void* const* d_in, const int* in_sizes, int n_in,
                              void* d_out, int out_size) {
    const float* x    = (const float*)d_in[0];
    const float* Wih  = (const float*)d_in[1];
    const float* Whh  = (const float*)d_in[2];
    const float* bih  = (const float*)d_in[3];
    const float* bhh  = (const float*)d_in[4];
    const float* fcW  = (const float*)d_in[5];
    const float* fcb  = (const float*)d_in[6];
    float* out = (float*)d_out;

    cudaFuncSetAttribute(lstm_fused_kernel,
                         cudaFuncAttributeMaxDynamicSharedMemorySize, SMEM_TOTAL);
    lstm_fused_kernel<<<B_SZ / BR, NTH, SMEM_TOTAL>>>(x, Wih, Whh, bih, bhh, fcW, fcb, out);
}